// round 10
// baseline (speedup 1.0000x reference)
#include <cuda_runtime.h>
#include <math.h>
#include <stdint.h>

// Problem dims (fixed by the dataset)
#define BB 32
#define DD 1024
#define HH 1024

#define GEMM_BLOCKS 32        // h-tiles of 32: 1024/32
#define STREAM_BLOCKS 1024
#define NTHREADS 256
#define N4 ((BB*DD*HH)/4)     // 8388608 float4

// stream: per-block chunk 8192 f4 (128KB) = 16 stages x 512 f4 (8KB)
#define ST_F4 512
#define NST 16
#define RING 3                // load slots in flight
#define ORING 2               // store slots
#define STAGE_BYTES (ST_F4 * 16)   // 8192

// d_out layout (float32, reference return order):
//   out [B,H] @0 ; u_new [B,H] @32768 ; E_w [B,D,H] @65536 ; E_b @65536+2^25
#define OFF_UNEW (BB*HH)
#define OFF_EW   (2*BB*HH)
#define OFF_EB   (2*BB*HH + BB*DD*HH)

struct SmemStream {
    float4 inb[RING][ST_F4];     // 24KB
    float4 outb[ORING][ST_F4];   // 16KB
    unsigned long long mbar[RING];
};
struct SmemGemm {
    float xs[32][33];
    float ws[32][32];
};

__device__ __forceinline__ uint32_t smem_u32(const void* p) {
    return (uint32_t)__cvta_generic_to_shared(p);
}
__device__ __forceinline__ void mbar_init(uint32_t mbar, uint32_t count) {
    asm volatile("mbarrier.init.shared.b64 [%0], %1;" :: "r"(mbar), "r"(count) : "memory");
}
__device__ __forceinline__ void mbar_expect_tx(uint32_t mbar, uint32_t bytes) {
    asm volatile("mbarrier.arrive.expect_tx.shared.b64 _, [%0], %1;"
                 :: "r"(mbar), "r"(bytes) : "memory");
}
__device__ __forceinline__ void mbar_wait(uint32_t mbar, uint32_t phase) {
    asm volatile(
        "{\n\t.reg .pred P;\n\t"
        "W%=:\n\t"
        "mbarrier.try_wait.parity.shared::cta.b64 P, [%0], %1, 0x989680;\n\t"
        "@!P bra W%=;\n\t}"
        :: "r"(mbar), "r"(phase) : "memory");
}
__device__ __forceinline__ void bulk_g2s(uint32_t sdst, const void* gsrc,
                                         uint32_t bytes, uint32_t mbar) {
    asm volatile(
        "cp.async.bulk.shared::cta.global.mbarrier::complete_tx::bytes "
        "[%0], [%1], %2, [%3];"
        :: "r"(sdst), "l"(gsrc), "r"(bytes), "r"(mbar) : "memory");
}
__device__ __forceinline__ void bulk_s2g(void* gdst, uint32_t ssrc, uint32_t bytes) {
    asm volatile("cp.async.bulk.global.shared::cta.bulk_group [%0], [%1], %2;"
                 :: "l"(gdst), "r"(ssrc), "r"(bytes) : "memory");
}

__global__ void diag_rtrl_fused_kernel(
    const float* __restrict__ x,   // [B,D]
    const float* __restrict__ w,   // [D,H]
    const float* __restrict__ b,   // [H]
    const float* __restrict__ u,   // [B,H]
    const float* __restrict__ Ew,  // [1,B,D,H]
    const float* __restrict__ Eb,  // [1,B,H]
    float* __restrict__ out)       // packed outputs
{
    __shared__ __align__(16) union { SmemStream s; SmemGemm g; } sm;

    if (blockIdx.x >= GEMM_BLOCKS) {
        // ---------- E_w stream on the TMA bulk engine ----------
        // E_new_w[i,d,h] = 0.9*E_w[i,d,h] + x[i,d]
        const int t     = threadIdx.x;
        const int cbase = (blockIdx.x - GEMM_BLOCKS) * (ST_F4 * NST); // f4 idx
        const float4* __restrict__ gin  = reinterpret_cast<const float4*>(Ew) + cbase;
        float4* __restrict__ gout = reinterpret_cast<float4*>(&out[OFF_EW]) + cbase;

        const uint32_t mb0  = smem_u32(&sm.s.mbar[0]);
        const uint32_t inb0 = smem_u32(&sm.s.inb[0][0]);
        const uint32_t oub0 = smem_u32(&sm.s.outb[0][0]);

        if (t == 0) {
            mbar_init(mb0, 1);
            mbar_init(mb0 + 8, 1);
            mbar_init(mb0 + 16, 1);
        }
        __syncthreads();

        if (t == 0) {
            #pragma unroll
            for (int s = 0; s < RING; s++) {
                mbar_expect_tx(mb0 + 8 * s, STAGE_BYTES);
                bulk_g2s(inb0 + s * STAGE_BYTES, gin + s * ST_F4,
                         STAGE_BYTES, mb0 + 8 * s);
            }
        }

        #pragma unroll 1
        for (int s = 0; s < NST; s++) {
            const int slot  = s % RING;
            const int oslot = s & 1;
            const uint32_t ph = (uint32_t)(s / RING) & 1u;

            // 1. stage data arrived
            mbar_wait(mb0 + 8 * slot, ph);
            // 2. out slot from stage s-2 drained (<=1 group outstanding)
            if (t == 0)
                asm volatile("cp.async.bulk.wait_group.read 1;" ::: "memory");
            // 3. order 2 before anyone writes outb
            __syncthreads();

            // 4. compute: 2 f4 per thread
            {
                const int li = 2 * t;
                float4 e0 = sm.s.inb[slot][li];
                float4 e1 = sm.s.inb[slot][li + 1];
                const int g = cbase + s * ST_F4 + li;
                const float xv = __ldg(&x[g >> 8]);
                float4 r0, r1;
                r0.x = fmaf(0.9f, e0.x, xv); r0.y = fmaf(0.9f, e0.y, xv);
                r0.z = fmaf(0.9f, e0.z, xv); r0.w = fmaf(0.9f, e0.w, xv);
                r1.x = fmaf(0.9f, e1.x, xv); r1.y = fmaf(0.9f, e1.y, xv);
                r1.z = fmaf(0.9f, e1.z, xv); r1.w = fmaf(0.9f, e1.w, xv);
                sm.s.outb[oslot][li]     = r0;
                sm.s.outb[oslot][li + 1] = r1;
            }
            // 5. outb fully written; inb[slot] fully read
            __syncthreads();

            // 6. issue store; refill this load slot
            if (t == 0) {
                asm volatile("fence.proxy.async.shared::cta;" ::: "memory");
                bulk_s2g(gout + s * ST_F4, oub0 + oslot * STAGE_BYTES,
                         STAGE_BYTES);
                asm volatile("cp.async.bulk.commit_group;" ::: "memory");
                if (s + RING < NST) {
                    mbar_expect_tx(mb0 + 8 * slot, STAGE_BYTES);
                    bulk_g2s(inb0 + slot * STAGE_BYTES,
                             gin + (s + RING) * ST_F4,
                             STAGE_BYTES, mb0 + 8 * slot);
                }
            }
        }
        // kernel boundary flushes remaining bulk stores
    } else {
        // ---------------- GEMM + epilogue path ----------------
        const int t  = threadIdx.x;
        const int h0 = blockIdx.x * 32;
        const int hx = t & 7;
        const int i  = t >> 3;

        float4 acc = make_float4(0.f, 0.f, 0.f, 0.f);

        for (int kt = 0; kt < DD; kt += 32) {
            for (int m = t; m < 1024; m += NTHREADS)
                sm.g.xs[m >> 5][m & 31] = x[(m >> 5) * DD + kt + (m & 31)];
            for (int m = t; m < 1024; m += NTHREADS)
                sm.g.ws[m >> 5][m & 31] = w[(kt + (m >> 5)) * HH + h0 + (m & 31)];
            __syncthreads();

            #pragma unroll 8
            for (int k = 0; k < 32; k++) {
                float4 wv = reinterpret_cast<const float4*>(&sm.g.ws[k][0])[hx];
                float xv = sm.g.xs[i][k];
                acc.x = fmaf(xv, wv.x, acc.x);
                acc.y = fmaf(xv, wv.y, acc.y);
                acc.z = fmaf(xv, wv.z, acc.z);
                acc.w = fmaf(xv, wv.w, acc.w);
            }
            __syncthreads();
        }

        const int h   = h0 + hx * 4;
        const int idx = i * HH + h;
        float4 bv = *reinterpret_cast<const float4*>(&b[h]);
        float4 uv = *reinterpret_cast<const float4*>(&u[idx]);
        float4 z;
        z.x = fmaf(0.9f, uv.x, acc.x + bv.x);
        z.y = fmaf(0.9f, uv.y, acc.y + bv.y);
        z.z = fmaf(0.9f, uv.z, acc.z + bv.z);
        z.w = fmaf(0.9f, uv.w, acc.w + bv.w);

        *reinterpret_cast<float4*>(&out[OFF_UNEW + idx]) = z;

        float4 o;
        o.x = tanhf(z.x); o.y = tanhf(z.y);
        o.z = tanhf(z.z); o.w = tanhf(z.w);
        *reinterpret_cast<float4*>(&out[idx]) = o;

        float4 ev = *reinterpret_cast<const float4*>(&Eb[idx]);
        float4 e;
        e.x = fmaf(0.9f, ev.x, 1.0f);
        e.y = fmaf(0.9f, ev.y, 1.0f);
        e.z = fmaf(0.9f, ev.z, 1.0f);
        e.w = fmaf(0.9f, ev.w, 1.0f);
        *reinterpret_cast<float4*>(&out[OFF_EB + idx]) = e;
    }
}

extern "C" void kernel_launch(void* const* d_in, const int* in_sizes, int n_in,
                              void* d_out, int out_size) {
    const float* x  = (const float*)d_in[0];  // [32,1024]
    const float* w  = (const float*)d_in[1];  // [1024,1024]
    const float* b  = (const float*)d_in[2];  // [1024]
    const float* u  = (const float*)d_in[3];  // [32,1024]
    const float* Ew = (const float*)d_in[4];  // [1,32,1024,1024]
    const float* Eb = (const float*)d_in[5];  // [1,32,1024]
    float* out = (float*)d_out;

    diag_rtrl_fused_kernel<<<GEMM_BLOCKS + STREAM_BLOCKS, NTHREADS>>>(
        x, w, b, u, Ew, Eb, out);
}

// round 12
// speedup vs baseline: 1.1071x; 1.1071x over previous
#include <cuda_runtime.h>
#include <math.h>
#include <stdint.h>

// Problem dims (fixed by the dataset)
#define BB 32
#define DD 1024
#define HH 1024

#define GEMM_BLOCKS 16      // h-tiles of 64: 1024/64
#define STREAM_BLOCKS 1168
#define NTHREADS 256

// d_out layout (float32, reference return order):
//   out   [B,H]      @ 0
//   u_new [B,H]      @ 32768
//   E_w   [B,D,H]    @ 65536
//   E_b   [B,H]      @ 65536 + 33554432
#define OFF_UNEW (BB*HH)
#define OFF_EW   (2*BB*HH)
#define OFF_EB   (2*BB*HH + BB*DD*HH)

// 256-bit E_w read with L2 evict_last (stays resident across graph replays).
// ptxas on this toolchain requires .v4.b64 width for the evict_last modifier.
#define LDG256_EL(v0, v1, v2, v3, ptr)                                     \
    asm("ld.global.L2::evict_last.v4.b64 {%0,%1,%2,%3}, [%4];"             \
        : "=l"(v0), "=l"(v1), "=l"(v2), "=l"(v3) : "l"(ptr))
// 256-bit streaming store (evict-first; don't thrash cached reads)
#define STG256_CS(ptr, v0, v1, v2, v3)                                     \
    asm("st.global.cs.v4.b64 [%0], {%1,%2,%3,%4};"                         \
        :: "l"(ptr), "l"(v0), "l"(v1), "l"(v2), "l"(v3) : "memory")

__device__ __forceinline__ uint64_t fma2_u64(uint64_t e, float xv) {
    float2 f = *reinterpret_cast<float2*>(&e);
    f.x = fmaf(0.9f, f.x, xv);
    f.y = fmaf(0.9f, f.y, xv);
    return *reinterpret_cast<uint64_t*>(&f);
}

__global__ void diag_rtrl_fused_kernel(
    const float* __restrict__ x,   // [B,D]
    const float* __restrict__ w,   // [D,H]
    const float* __restrict__ b,   // [H]
    const float* __restrict__ u,   // [B,H]
    const float* __restrict__ Ew,  // [1,B,D,H]
    const float* __restrict__ Eb,  // [1,B,H]
    float* __restrict__ out)       // packed outputs
{
    if (blockIdx.x < GEMM_BLOCKS) {
        // ---------------- GEMM + epilogue path ----------------
        // block handles h-tile of 64 columns, all 32 batch rows.
        __shared__ float xs[32][33];                  // [i][k] (+pad)
        __shared__ __align__(16) float ws[32][64];    // [k][h]

        const int t  = threadIdx.x;
        const int h0 = blockIdx.x * 64;
        const int hx = t & 15;          // which float4 of the h-tile
        const int iy = t >> 4;          // 0..15 -> batch-row pair
        const int i0 = iy * 2;

        float4 acc0 = make_float4(0.f, 0.f, 0.f, 0.f);
        float4 acc1 = make_float4(0.f, 0.f, 0.f, 0.f);

        for (int kt = 0; kt < DD; kt += 32) {
            // load x tile: 32 rows x 32 k (coalesced: 32 floats per row)
            for (int m = t; m < 1024; m += NTHREADS) {
                xs[m >> 5][m & 31] = x[(m >> 5) * DD + kt + (m & 31)];
            }
            // load w tile: 32 k x 64 h (coalesced)
            for (int m = t; m < 2048; m += NTHREADS) {
                ws[m >> 6][m & 63] = w[(kt + (m >> 6)) * HH + h0 + (m & 63)];
            }
            __syncthreads();

            #pragma unroll 8
            for (int k = 0; k < 32; k++) {
                float4 wv = reinterpret_cast<const float4*>(&ws[k][0])[hx];
                float x0 = xs[i0][k];
                float x1 = xs[i0 + 1][k];
                acc0.x = fmaf(x0, wv.x, acc0.x);
                acc0.y = fmaf(x0, wv.y, acc0.y);
                acc0.z = fmaf(x0, wv.z, acc0.z);
                acc0.w = fmaf(x0, wv.w, acc0.w);
                acc1.x = fmaf(x1, wv.x, acc1.x);
                acc1.y = fmaf(x1, wv.y, acc1.y);
                acc1.z = fmaf(x1, wv.z, acc1.z);
                acc1.w = fmaf(x1, wv.w, acc1.w);
            }
            __syncthreads();
        }

        // epilogue: z = 0.9*u + x@w + b ; out = tanh(z); u_new = z; E_b update
        const int h = h0 + hx * 4;
        float4 bv = *reinterpret_cast<const float4*>(&b[h]);

        #pragma unroll
        for (int ii = 0; ii < 2; ii++) {
            const int i = i0 + ii;
            const int idx = i * HH + h;
            float4 a  = ii ? acc1 : acc0;
            float4 uv = *reinterpret_cast<const float4*>(&u[idx]);
            float4 z;
            z.x = fmaf(0.9f, uv.x, a.x + bv.x);
            z.y = fmaf(0.9f, uv.y, a.y + bv.y);
            z.z = fmaf(0.9f, uv.z, a.z + bv.z);
            z.w = fmaf(0.9f, uv.w, a.w + bv.w);

            // u_new
            *reinterpret_cast<float4*>(&out[OFF_UNEW + idx]) = z;
            // out = tanh(z)
            float4 o;
            o.x = tanhf(z.x); o.y = tanhf(z.y);
            o.z = tanhf(z.z); o.w = tanhf(z.w);
            *reinterpret_cast<float4*>(&out[idx]) = o;
            // E_b_new = 0.9*E_b + 1
            float4 ev = *reinterpret_cast<const float4*>(&Eb[idx]);
            float4 e;
            e.x = fmaf(0.9f, ev.x, 1.0f);
            e.y = fmaf(0.9f, ev.y, 1.0f);
            e.z = fmaf(0.9f, ev.z, 1.0f);
            e.w = fmaf(0.9f, ev.w, 1.0f);
            *reinterpret_cast<float4*>(&out[OFF_EB + idx]) = e;
        }
    } else {
        // ---------------- E_w streaming path (256-bit) ----------------
        // E_new_w[i,d,h] = 0.9*E_w[i,d,h] + x[i,d]
        // 32B index q -> elements [8q, 8q+8) -> single x index q>>7
        const int N8 = (BB * DD * HH) / 8;  // 4194304 32B-chunks
        const char* ein = reinterpret_cast<const char*>(Ew);
        char* eo = reinterpret_cast<char*>(&out[OFF_EW]);

        const int stride = (gridDim.x - GEMM_BLOCKS) * NTHREADS;
        int q = (blockIdx.x - GEMM_BLOCKS) * NTHREADS + threadIdx.x;

        for (; q < N8; q += stride) {
            uint64_t v0, v1, v2, v3;
            LDG256_EL(v0, v1, v2, v3, ein + (size_t)q * 32);
            const float xv = __ldg(&x[q >> 7]);
            v0 = fma2_u64(v0, xv);
            v1 = fma2_u64(v1, xv);
            v2 = fma2_u64(v2, xv);
            v3 = fma2_u64(v3, xv);
            STG256_CS(eo + (size_t)q * 32, v0, v1, v2, v3);
        }
    }
}

extern "C" void kernel_launch(void* const* d_in, const int* in_sizes, int n_in,
                              void* d_out, int out_size) {
    const float* x  = (const float*)d_in[0];  // [32,1024]
    const float* w  = (const float*)d_in[1];  // [1024,1024]
    const float* b  = (const float*)d_in[2];  // [1024]
    const float* u  = (const float*)d_in[3];  // [32,1024]
    const float* Ew = (const float*)d_in[4];  // [1,32,1024,1024]
    const float* Eb = (const float*)d_in[5];  // [1,32,1024]
    float* out = (float*)d_out;

    diag_rtrl_fused_kernel<<<GEMM_BLOCKS + STREAM_BLOCKS, NTHREADS>>>(
        x, w, b, u, Ew, Eb, out);
}

// round 13
// speedup vs baseline: 1.5777x; 1.4251x over previous
#include <cuda_runtime.h>
#include <math.h>

// Problem dims (fixed by the dataset)
#define BB 32
#define DD 1024
#define HH 1024

#define GEMM_BLOCKS 16      // h-tiles of 64: 1024/64
#define STREAM_BLOCKS 1568  // grid 1584 ~= 1.33 x (148 SMs * 8 blocks)
#define NTHREADS 256

// d_out layout (float32, reference return order):
//   out   [B,H]      @ 0
//   u_new [B,H]      @ 32768
//   E_w   [B,D,H]    @ 65536
//   E_b   [B,H]      @ 65536 + 33554432
#define OFF_UNEW (BB*HH)
#define OFF_EW   (2*BB*HH)
#define OFF_EB   (2*BB*HH + BB*DD*HH)

__global__ void __launch_bounds__(NTHREADS, 8)
diag_rtrl_fused_kernel(
    const float* __restrict__ x,   // [B,D]
    const float* __restrict__ w,   // [D,H]
    const float* __restrict__ b,   // [H]
    const float* __restrict__ u,   // [B,H]
    const float* __restrict__ Ew,  // [1,B,D,H]
    const float* __restrict__ Eb,  // [1,B,H]
    float* __restrict__ out)       // packed outputs
{
    if (blockIdx.x < GEMM_BLOCKS) {
        // ---------------- GEMM + epilogue path ----------------
        // block handles h-tile of 64 columns, all 32 batch rows.
        __shared__ float xs[32][33];                  // [i][k] (+pad)
        __shared__ __align__(16) float ws[32][64];    // [k][h]

        const int t  = threadIdx.x;
        const int h0 = blockIdx.x * 64;
        const int hx = t & 15;          // which float4 of the h-tile
        const int iy = t >> 4;          // 0..15 -> batch-row pair
        const int i0 = iy * 2;

        float4 acc0 = make_float4(0.f, 0.f, 0.f, 0.f);
        float4 acc1 = make_float4(0.f, 0.f, 0.f, 0.f);

        for (int kt = 0; kt < DD; kt += 32) {
            // load x tile: 32 rows x 32 k (coalesced: 32 floats per row)
            for (int m = t; m < 1024; m += NTHREADS) {
                xs[m >> 5][m & 31] = x[(m >> 5) * DD + kt + (m & 31)];
            }
            // load w tile: 32 k x 64 h (coalesced)
            for (int m = t; m < 2048; m += NTHREADS) {
                ws[m >> 6][m & 63] = w[(kt + (m >> 6)) * HH + h0 + (m & 63)];
            }
            __syncthreads();

            #pragma unroll 8
            for (int k = 0; k < 32; k++) {
                float4 wv = reinterpret_cast<const float4*>(&ws[k][0])[hx];
                float x0 = xs[i0][k];
                float x1 = xs[i0 + 1][k];
                acc0.x = fmaf(x0, wv.x, acc0.x);
                acc0.y = fmaf(x0, wv.y, acc0.y);
                acc0.z = fmaf(x0, wv.z, acc0.z);
                acc0.w = fmaf(x0, wv.w, acc0.w);
                acc1.x = fmaf(x1, wv.x, acc1.x);
                acc1.y = fmaf(x1, wv.y, acc1.y);
                acc1.z = fmaf(x1, wv.z, acc1.z);
                acc1.w = fmaf(x1, wv.w, acc1.w);
            }
            __syncthreads();
        }

        // epilogue: z = 0.9*u + x@w + b ; out = tanh(z); u_new = z; E_b update
        const int h = h0 + hx * 4;
        float4 bv = *reinterpret_cast<const float4*>(&b[h]);

        #pragma unroll
        for (int ii = 0; ii < 2; ii++) {
            const int i = i0 + ii;
            const int idx = i * HH + h;
            float4 a  = ii ? acc1 : acc0;
            float4 uv = *reinterpret_cast<const float4*>(&u[idx]);
            float4 z;
            z.x = fmaf(0.9f, uv.x, a.x + bv.x);
            z.y = fmaf(0.9f, uv.y, a.y + bv.y);
            z.z = fmaf(0.9f, uv.z, a.z + bv.z);
            z.w = fmaf(0.9f, uv.w, a.w + bv.w);

            // u_new
            *reinterpret_cast<float4*>(&out[OFF_UNEW + idx]) = z;
            // out = tanh(z)
            float4 o;
            o.x = tanhf(z.x); o.y = tanhf(z.y);
            o.z = tanhf(z.z); o.w = tanhf(z.w);
            *reinterpret_cast<float4*>(&out[idx]) = o;
            // E_b_new = 0.9*E_b + 1
            float4 ev = *reinterpret_cast<const float4*>(&Eb[idx]);
            float4 e;
            e.x = fmaf(0.9f, ev.x, 1.0f);
            e.y = fmaf(0.9f, ev.y, 1.0f);
            e.z = fmaf(0.9f, ev.z, 1.0f);
            e.w = fmaf(0.9f, ev.w, 1.0f);
            *reinterpret_cast<float4*>(&out[OFF_EB + idx]) = e;
        }
    } else {
        // ---------------- E_w streaming path (R1 body, unchanged) -------
        // E_new_w[i,d,h] = 0.9*E_w[i,d,h] + x[i,d]
        // float4 index p -> element 4p -> x index (4p)>>10 = p>>8
        const int N4 = (BB * DD * HH) / 4;  // 8388608
        const float4* ein = reinterpret_cast<const float4*>(Ew);
        float4* eo = reinterpret_cast<float4*>(&out[OFF_EW]);

        const int stride = (gridDim.x - GEMM_BLOCKS) * NTHREADS;
        int p = (blockIdx.x - GEMM_BLOCKS) * NTHREADS + threadIdx.x;

        for (; p < N4; p += stride) {
            float4 e = __ldcs(ein + p);
            float xv = __ldg(&x[p >> 8]);
            float4 r;
            r.x = fmaf(0.9f, e.x, xv);
            r.y = fmaf(0.9f, e.y, xv);
            r.z = fmaf(0.9f, e.z, xv);
            r.w = fmaf(0.9f, e.w, xv);
            __stcs(eo + p, r);
        }
    }
}

extern "C" void kernel_launch(void* const* d_in, const int* in_sizes, int n_in,
                              void* d_out, int out_size) {
    const float* x  = (const float*)d_in[0];  // [32,1024]
    const float* w  = (const float*)d_in[1];  // [1024,1024]
    const float* b  = (const float*)d_in[2];  // [1024]
    const float* u  = (const float*)d_in[3];  // [32,1024]
    const float* Ew = (const float*)d_in[4];  // [1,32,1024,1024]
    const float* Eb = (const float*)d_in[5];  // [1,32,1024]
    float* out = (float*)d_out;

    diag_rtrl_fused_kernel<<<GEMM_BLOCKS + STREAM_BLOCKS, NTHREADS>>>(
        x, w, b, u, Ew, Eb, out);
}

// round 15
// speedup vs baseline: 1.9084x; 1.2096x over previous
#include <cuda_runtime.h>
#include <math.h>

// Problem dims (fixed by the dataset)
#define BB 32
#define DD 1024
#define HH 1024

#define GEMM_BLOCKS 16      // h-tiles of 64: 1024/64
#define STREAM_BLOCKS 1168
#define NTHREADS 256

// d_out layout (float32, reference return order):
//   out   [B,H]      @ 0
//   u_new [B,H]      @ 32768
//   E_w   [B,D,H]    @ 65536
//   E_b   [B,H]      @ 65536 + 33554432
#define OFF_UNEW (BB*HH)
#define OFF_EW   (2*BB*HH)
#define OFF_EB   (2*BB*HH + BB*DD*HH)

__global__ void diag_rtrl_fused_kernel(
    const float* __restrict__ x,   // [B,D]
    const float* __restrict__ w,   // [D,H]
    const float* __restrict__ b,   // [H]
    const float* __restrict__ u,   // [B,H]
    const float* __restrict__ Ew,  // [1,B,D,H]
    const float* __restrict__ Eb,  // [1,B,H]
    float* __restrict__ out)       // packed outputs
{
    if (blockIdx.x < GEMM_BLOCKS) {
        // ---------------- GEMM + epilogue path ----------------
        // block handles h-tile of 64 columns, all 32 batch rows.
        __shared__ float xs[32][33];                  // [i][k] (+pad)
        __shared__ __align__(16) float ws[32][64];    // [k][h]

        const int t  = threadIdx.x;
        const int h0 = blockIdx.x * 64;
        const int hx = t & 15;          // which float4 of the h-tile
        const int iy = t >> 4;          // 0..15 -> batch-row pair
        const int i0 = iy * 2;

        float4 acc0 = make_float4(0.f, 0.f, 0.f, 0.f);
        float4 acc1 = make_float4(0.f, 0.f, 0.f, 0.f);

        for (int kt = 0; kt < DD; kt += 32) {
            // load x tile: 32 rows x 32 k (coalesced: 32 floats per row)
            for (int m = t; m < 1024; m += NTHREADS) {
                xs[m >> 5][m & 31] = x[(m >> 5) * DD + kt + (m & 31)];
            }
            // load w tile: 32 k x 64 h (coalesced)
            for (int m = t; m < 2048; m += NTHREADS) {
                ws[m >> 6][m & 63] = w[(kt + (m >> 6)) * HH + h0 + (m & 63)];
            }
            __syncthreads();

            #pragma unroll 8
            for (int k = 0; k < 32; k++) {
                float4 wv = reinterpret_cast<const float4*>(&ws[k][0])[hx];
                float x0 = xs[i0][k];
                float x1 = xs[i0 + 1][k];
                acc0.x = fmaf(x0, wv.x, acc0.x);
                acc0.y = fmaf(x0, wv.y, acc0.y);
                acc0.z = fmaf(x0, wv.z, acc0.z);
                acc0.w = fmaf(x0, wv.w, acc0.w);
                acc1.x = fmaf(x1, wv.x, acc1.x);
                acc1.y = fmaf(x1, wv.y, acc1.y);
                acc1.z = fmaf(x1, wv.z, acc1.z);
                acc1.w = fmaf(x1, wv.w, acc1.w);
            }
            __syncthreads();
        }

        // epilogue: z = 0.9*u + x@w + b ; out = tanh(z); u_new = z; E_b update
        const int h = h0 + hx * 4;
        float4 bv = *reinterpret_cast<const float4*>(&b[h]);

        #pragma unroll
        for (int ii = 0; ii < 2; ii++) {
            const int i = i0 + ii;
            const int idx = i * HH + h;
            float4 a  = ii ? acc1 : acc0;
            float4 uv = *reinterpret_cast<const float4*>(&u[idx]);
            float4 z;
            z.x = fmaf(0.9f, uv.x, a.x + bv.x);
            z.y = fmaf(0.9f, uv.y, a.y + bv.y);
            z.z = fmaf(0.9f, uv.z, a.z + bv.z);
            z.w = fmaf(0.9f, uv.w, a.w + bv.w);

            // u_new
            *reinterpret_cast<float4*>(&out[OFF_UNEW + idx]) = z;
            // out = tanh(z)
            float4 o;
            o.x = tanhf(z.x); o.y = tanhf(z.y);
            o.z = tanhf(z.z); o.w = tanhf(z.w);
            *reinterpret_cast<float4*>(&out[idx]) = o;
            // E_b_new = 0.9*E_b + 1
            float4 ev = *reinterpret_cast<const float4*>(&Eb[idx]);
            float4 e;
            e.x = fmaf(0.9f, ev.x, 1.0f);
            e.y = fmaf(0.9f, ev.y, 1.0f);
            e.z = fmaf(0.9f, ev.z, 1.0f);
            e.w = fmaf(0.9f, ev.w, 1.0f);
            *reinterpret_cast<float4*>(&out[OFF_EB + idx]) = e;
        }
    } else {
        // ---------------- E_w streaming path ----------------
        // E_new_w[i,d,h] = 0.9*E_w[i,d,h] + x[i,d]
        // float4 index p -> element 4p -> x index (4p)>>10 = p>>8
        const int N4 = (BB * DD * HH) / 4;  // 8388608
        const float4* ein = reinterpret_cast<const float4*>(Ew);
        float4* eo = reinterpret_cast<float4*>(&out[OFF_EW]);

        const int stride = (gridDim.x - GEMM_BLOCKS) * NTHREADS;
        int p = (blockIdx.x - GEMM_BLOCKS) * NTHREADS + threadIdx.x;

        for (; p < N4; p += stride) {
            float4 e = __ldcs(ein + p);
            float xv = __ldg(&x[p >> 8]);
            float4 r;
            r.x = fmaf(0.9f, e.x, xv);
            r.y = fmaf(0.9f, e.y, xv);
            r.z = fmaf(0.9f, e.z, xv);
            r.w = fmaf(0.9f, e.w, xv);
            __stcs(eo + p, r);
        }
    }
}

extern "C" void kernel_launch(void* const* d_in, const int* in_sizes, int n_in,
                              void* d_out, int out_size) {
    const float* x  = (const float*)d_in[0];  // [32,1024]
    const float* w  = (const float*)d_in[1];  // [1024,1024]
    const float* b  = (const float*)d_in[2];  // [1024]
    const float* u  = (const float*)d_in[3];  // [32,1024]
    const float* Ew = (const float*)d_in[4];  // [1,32,1024,1024]
    const float* Eb = (const float*)d_in[5];  // [1,32,1024]
    float* out = (float*)d_out;

    diag_rtrl_fused_kernel<<<GEMM_BLOCKS + STREAM_BLOCKS, NTHREADS>>>(
        x, w, b, u, Ew, Eb, out);
}